// round 1
// baseline (speedup 1.0000x reference)
#include <cuda_runtime.h>

namespace {
constexpr int Hn = 1024;   // time steps
constexpr int Bn = 1024;   // batteries

__device__ __forceinline__ float tanh_fast(float x){ float r; asm("tanh.approx.f32 %0, %1;" : "=f"(r) : "f"(x)); return r; }
__device__ __forceinline__ float ex2_fast (float x){ float r; asm("ex2.approx.ftz.f32 %0, %1;" : "=f"(r) : "f"(x)); return r; }
__device__ __forceinline__ float lg2_fast (float x){ float r; asm("lg2.approx.ftz.f32 %0, %1;" : "=f"(r) : "f"(x)); return r; }
__device__ __forceinline__ float rcp_fast (float x){ float r; asm("rcp.approx.ftz.f32 %0, %1;" : "=f"(r) : "f"(x)); return r; }
// softplus in log2 domain: log2(1 + exp(x)); caller folds ln2 into its scale.
__device__ __forceinline__ float sp_l2(float x){ return lg2_fast(1.0f + ex2_fast(x * 1.4426950408889634f)); }
}

// 2 batteries per warp; 16 lanes per battery. Lane g owns hp units {g+16k, k<8}
// and hr units {g+16k, k<4}. Butterfly xor-reduce (1,2,4,8) stays inside the
// 16-lane half and leaves the sums replicated in every lane (no broadcast).
__global__ void __launch_bounds__(64, 1) dci_rollout(
    const float* __restrict__ gI, const float* __restrict__ gT, const float* __restrict__ soc0,
    const float* __restrict__ W1p, const float* __restrict__ b1p,
    const float* __restrict__ W2p, const float* __restrict__ b2p,
    const float* __restrict__ W1r, const float* __restrict__ b1r,
    const float* __restrict__ W2r, const float* __restrict__ b2r,
    float* __restrict__ out)
{
    const int tid  = blockIdx.x * blockDim.x + threadIdx.x;
    const int lane = threadIdx.x & 31;
    const int g    = lane & 15;
    const int bat  = (tid >> 5) * 2 + (lane >> 4);

    // --- weights into registers (one-time) ---
    float w0[8], w1[8], w2[8], wb[8];
    float4 wp[8];
#pragma unroll
    for (int k = 0; k < 8; ++k) {
        int u = g + 16 * k;
        w0[k] = W1p[u]; w1[k] = W1p[128 + u]; w2[k] = W1p[256 + u]; wb[k] = b1p[u];
        wp[k] = reinterpret_cast<const float4*>(W2p)[u];   // [R0,R1,C1,Q] row u
    }
    float q0[4], q1[4], q2[4], qb[4], qw[4];
#pragma unroll
    for (int k = 0; k < 4; ++k) {
        int u = g + 16 * k;
        q0[k] = W1r[u]; q1[k] = W1r[64 + u]; q2[k] = W1r[128 + u]; qb[k] = b1r[u];
        qw[k] = W2r[u];
    }
    const float4 b2 = *reinterpret_cast<const float4*>(b2p);
    const float  br = b2r[0];

    constexpr float LN2 = 0.6931471805599453f;
    constexpr float EPS = 1e-6f;

    float s0  = soc0[bat];
    float soc = (s0 == s0) ? s0 : 0.8f;   // NaN -> 0.8
    float v1  = 0.0f;

    const float* Ib = gI + bat * Hn;
    const float* Tb = gT + bat * Hn;
    float It = __ldg(Ib), Tt = __ldg(Tb);
    float vkeep = 0.0f;
    float* orow = out + bat * Hn;

#pragma unroll 1
    for (int t = 0; t < Hn; ++t) {
        const int tn = (t + 1 < Hn) ? (t + 1) : (Hn - 1);
        const float In = __ldg(Ib + tn);
        const float Tn = __ldg(Tb + tn);

        // hidden layer (hp): one state-dependent FMA + tanh per unit
        float h[8];
#pragma unroll
        for (int k = 0; k < 8; ++k) {
            float pre = fmaf(It, w1[k], fmaf(Tt, w2[k], wb[k]));
            h[k] = tanh_fast(fmaf(soc, w0[k], pre));
        }

        // --- critical path: Q partial -> reduce -> softplus -> soc update ---
        float p3 = h[0] * wp[0].w;
#pragma unroll
        for (int k = 1; k < 8; ++k) p3 = fmaf(h[k], wp[k].w, p3);
        p3 += __shfl_xor_sync(0xffffffffu, p3, 1);
        p3 += __shfl_xor_sync(0xffffffffu, p3, 2);
        p3 += __shfl_xor_sync(0xffffffffu, p3, 4);
        p3 += __shfl_xor_sync(0xffffffffu, p3, 8);

        float lq   = sp_l2(p3 + b2.w);
        float Q    = fmaf(lq, 5.0f * LN2, EPS);
        float rq   = rcp_fast(Q);
        float socn = fmaf(It * (-1.0f / 3600.0f), rq, soc);   // DT=1
        socn = fminf(fmaxf(socn, 0.0f), 1.0f);

        // --- off-critical: R0/R1/C1 partials, resid head, v1, output ---
        float p0 = h[0] * wp[0].x, p1 = h[0] * wp[0].y, p2 = h[0] * wp[0].z;
#pragma unroll
        for (int k = 1; k < 8; ++k) {
            p0 = fmaf(h[k], wp[k].x, p0);
            p1 = fmaf(h[k], wp[k].y, p1);
            p2 = fmaf(h[k], wp[k].z, p2);
        }
        float pr = 0.0f;
#pragma unroll
        for (int k = 0; k < 4; ++k) {
            float pre = fmaf(It, q1[k], fmaf(Tt, q2[k], qb[k]));
            float hr  = tanh_fast(fmaf(soc, q0[k], pre));
            pr = fmaf(hr, qw[k], pr);
        }
#pragma unroll
        for (int d = 1; d <= 8; d <<= 1) {
            p0 += __shfl_xor_sync(0xffffffffu, p0, d);
            p1 += __shfl_xor_sync(0xffffffffu, p1, d);
            p2 += __shfl_xor_sync(0xffffffffu, p2, d);
            pr += __shfl_xor_sync(0xffffffffu, pr, d);
        }
        float R0 = fmaf(sp_l2(p0 + b2.x), 0.01f   * LN2, EPS);
        float R1 = fmaf(sp_l2(p1 + b2.y), 0.02f   * LN2, EPS);
        float C1 = fmaf(sp_l2(p2 + b2.z), 2000.0f * LN2, EPS);
        float resid = pr + br;

        float invC1 = rcp_fast(C1);
        float invRC = rcp_fast(R1 * C1);
        float v1n = fmaf(It, invC1, fmaf(-v1, invRC, v1));    // v1 - v1/(R1C1) + I/C1

        float ocv = fmaf(fmaf(fmaf(0.3f, socn, -0.5f), socn, 1.2f), socn, 3.0f);
        float Vp  = (ocv - fmaf(It, R0, v1n)) + resid;        // ocv - I*R0 - v1 + resid

        // buffer one value per lane; coalesced 16-wide row store every 16 steps
        if ((t & 15) == g)  vkeep = Vp;
        if ((t & 15) == 15) orow[(t & ~15) + g] = vkeep;

        soc = socn; v1 = v1n; It = In; Tt = Tn;
    }
}

extern "C" void kernel_launch(void* const* d_in, const int* in_sizes, int n_in,
                              void* d_out, int out_size)
{
    // inputs: V(unused), I, Tz, soc0, W1p, b1p, W2p, b2p, W1r, b1r, W2r, b2r
    const float* I    = (const float*)d_in[1];
    const float* Tz   = (const float*)d_in[2];
    const float* soc0 = (const float*)d_in[3];
    const float* W1p  = (const float*)d_in[4];
    const float* b1p  = (const float*)d_in[5];
    const float* W2p  = (const float*)d_in[6];
    const float* b2p  = (const float*)d_in[7];
    const float* W1r  = (const float*)d_in[8];
    const float* b1r  = (const float*)d_in[9];
    const float* W2r  = (const float*)d_in[10];
    const float* b2r  = (const float*)d_in[11];
    float* out = (float*)d_out;

    // 512 warps = 1024 batteries (2 per warp); 256 blocks x 64 threads
    dci_rollout<<<256, 64>>>(I, Tz, soc0, W1p, b1p, W2p, b2p,
                             W1r, b1r, W2r, b2r, out);
}